// round 2
// baseline (speedup 1.0000x reference)
#include <cuda_runtime.h>
#include <math.h>

#define BSZ   2
#define NN    512
#define DIN   256
#define HEADS 8
#define DOUT  64
#define HD    512        // HEADS*DOUT
#define ROWS  1024       // BSZ*NN
#define ALPHA 0.2f

// Scratch (device globals: no allocation allowed in kernel_launch)
__device__ float g_src [ROWS * HD];
__device__ float g_tgt [ROWS * HD];
__device__ float g_skip[ROWS * HD];
__device__ float g_asrc[BSZ * HEADS * NN];   // [b][h][n]  = s_h . src
__device__ float g_atgt[BSZ * HEADS * NN];   // [b][h][m]  = s_h . tgt

// ---------------------------------------------------------------------------
// K1: three projections C = X @ W  (X:[1024,256], W:[256,512])
// 64x64 tile, 16 k-slab, 4x4 register micro-tile, 256 threads
// ---------------------------------------------------------------------------
__global__ void __launch_bounds__(256) gemm3_kernel(
    const float* __restrict__ X,
    const float* __restrict__ Wsrc,
    const float* __restrict__ Wtgt,
    const float* __restrict__ Wskip)
{
    const float* W = (blockIdx.z == 0) ? Wsrc : (blockIdx.z == 1) ? Wtgt : Wskip;
    float* C = (blockIdx.z == 0) ? g_src : (blockIdx.z == 1) ? g_tgt : g_skip;

    const int rowBase = blockIdx.y * 64;
    const int colBase = blockIdx.x * 64;

    __shared__ __align__(16) float As[16][72];   // pad 72: 4-way STS conflict max
    __shared__ __align__(16) float Bs[16][64];

    const int t  = threadIdx.x;
    const int ty = t >> 4, tx = t & 15;
    const int ak = t & 15, ar = t >> 4;   // A loader
    const int bc = t & 63, bk = t >> 6;   // B loader

    float acc[4][4];
#pragma unroll
    for (int i = 0; i < 4; i++)
#pragma unroll
        for (int j = 0; j < 4; j++) acc[i][j] = 0.f;

    for (int k0 = 0; k0 < DIN; k0 += 16) {
#pragma unroll
        for (int i = 0; i < 4; i++)
            As[ak][ar + 16 * i] = X[(size_t)(rowBase + ar + 16 * i) * DIN + k0 + ak];
#pragma unroll
        for (int i = 0; i < 4; i++)
            Bs[bk + 4 * i][bc] = W[(size_t)(k0 + bk + 4 * i) * HD + colBase + bc];
        __syncthreads();

#pragma unroll
        for (int kk = 0; kk < 16; kk++) {
            float4 a = *(const float4*)&As[kk][ty * 4];
            float4 b = *(const float4*)&Bs[kk][tx * 4];
            acc[0][0] = fmaf(a.x, b.x, acc[0][0]); acc[0][1] = fmaf(a.x, b.y, acc[0][1]);
            acc[0][2] = fmaf(a.x, b.z, acc[0][2]); acc[0][3] = fmaf(a.x, b.w, acc[0][3]);
            acc[1][0] = fmaf(a.y, b.x, acc[1][0]); acc[1][1] = fmaf(a.y, b.y, acc[1][1]);
            acc[1][2] = fmaf(a.y, b.z, acc[1][2]); acc[1][3] = fmaf(a.y, b.w, acc[1][3]);
            acc[2][0] = fmaf(a.z, b.x, acc[2][0]); acc[2][1] = fmaf(a.z, b.y, acc[2][1]);
            acc[2][2] = fmaf(a.z, b.z, acc[2][2]); acc[2][3] = fmaf(a.z, b.w, acc[2][3]);
            acc[3][0] = fmaf(a.w, b.x, acc[3][0]); acc[3][1] = fmaf(a.w, b.y, acc[3][1]);
            acc[3][2] = fmaf(a.w, b.z, acc[3][2]); acc[3][3] = fmaf(a.w, b.w, acc[3][3]);
        }
        __syncthreads();
    }

#pragma unroll
    for (int i = 0; i < 4; i++) {
        float4 v = make_float4(acc[i][0], acc[i][1], acc[i][2], acc[i][3]);
        *(float4*)&C[(size_t)(rowBase + ty * 4 + i) * HD + colBase + tx * 4] = v;
    }
}

// ---------------------------------------------------------------------------
// K1b: rank-1 terms  a_src[b,h,n] = s_h . src_row,  a_tgt[b,h,n] = s_h . tgt_row
// One block per (b,n) row; warp h handles head h.
// ---------------------------------------------------------------------------
__global__ void __launch_bounds__(256) rank1_kernel(const float* __restrict__ scoring)
{
    const int row  = blockIdx.x;        // 0..1023
    const int t    = threadIdx.x;
    const int h    = t >> 5;
    const int lane = t & 31;
    const int b = row >> 9, n = row & (NN - 1);

    const float s0 = scoring[h * 64 + lane];
    const float s1 = scoring[h * 64 + lane + 32];
    const float* sr = g_src + (size_t)row * HD + h * 64;
    const float* tr = g_tgt + (size_t)row * HD + h * 64;
    float vs = s0 * sr[lane] + s1 * sr[lane + 32];
    float vt = s0 * tr[lane] + s1 * tr[lane + 32];
#pragma unroll
    for (int off = 16; off; off >>= 1) {
        vs += __shfl_xor_sync(0xffffffffu, vs, off);
        vt += __shfl_xor_sync(0xffffffffu, vt, off);
    }
    if (lane == 0) {
        g_asrc[(size_t)(b * HEADS + h) * NN + n] = vs;
        g_atgt[(size_t)(b * HEADS + h) * NN + n] = vt;
    }
}

// ---------------------------------------------------------------------------
// K2: fused scores + mask + softmax + aggregation + skip + bias + ELU
// One block per (8 query rows, head, batch). 256 threads.
// ---------------------------------------------------------------------------
__global__ void __launch_bounds__(256) attn_kernel(
    const int*   __restrict__ adj,
    const float* __restrict__ scoring,
    const float* __restrict__ bias,
    float*       __restrict__ out)
{
    const int t     = threadIdx.x;
    const int nBase = blockIdx.x * 8;
    const int h     = blockIdx.y;
    const int b     = blockIdx.z;
    const int bh    = b * HEADS + h;

    __shared__ __align__(16) float sh_t[64][68];   // tgt / value tile (padded)
    __shared__ float sh_sc[8][512];                // scores -> probs -> combine buf
    __shared__ __align__(16) float sh_src[8][68];  // query src rows
    __shared__ __align__(16) float sh_s[64];       // 0.8 * scoring[h]
    __shared__ float sh_atgt[512];
    __shared__ float sh_asrc[8];
    __shared__ float sh_inv[8];

    // ---- prologue loads ----
    if (t < 16) {
        float4 v = *(const float4*)&scoring[h * 64 + t * 4];
        v.x *= (1.f - ALPHA); v.y *= (1.f - ALPHA);
        v.z *= (1.f - ALPHA); v.w *= (1.f - ALPHA);
        *(float4*)&sh_s[t * 4] = v;
    }
    sh_atgt[t]       = g_atgt[(size_t)bh * NN + t];
    sh_atgt[t + 256] = g_atgt[(size_t)bh * NN + t + 256];
    if (t < 8) sh_asrc[t] = g_asrc[(size_t)bh * NN + nBase + t];
    if (t < 128) {
        int r = t >> 4, c4 = t & 15;
        *(float4*)&sh_src[r][c4 * 4] =
            *(const float4*)&g_src[(size_t)(b * NN + nBase + r) * HD + h * 64 + c4 * 4];
    }
    __syncthreads();

    // ---- phase 1: scores ----
    const int n_loc = t >> 5;
    const int m0    = t & 31;
    const float a_n = sh_asrc[n_loc];
    const float* srow = &sh_src[n_loc][0];
    const size_t adjRow = (size_t)(b * NN + nBase + n_loc) * NN;

    for (int mt = 0; mt < NN; mt += 64) {
#pragma unroll
        for (int i = 0; i < 4; i++) {
            int idx = t + i * 256;
            int r = idx >> 4, c4 = idx & 15;
            *(float4*)&sh_t[r][c4 * 4] =
                *(const float4*)&g_tgt[(size_t)(b * NN + mt + r) * HD + h * 64 + c4 * 4];
        }
        __syncthreads();

        float acc0 = 0.f, acc1 = 0.f;
#pragma unroll
        for (int d4 = 0; d4 < 16; d4++) {
            float4 s4 = *(const float4*)&sh_s[d4 * 4];
            float4 a4 = *(const float4*)&srow[d4 * 4];
            float4 t0 = *(const float4*)&sh_t[m0][d4 * 4];
            float4 t1 = *(const float4*)&sh_t[m0 + 32][d4 * 4];
            acc0 = fmaf(s4.x, fmaxf(a4.x + t0.x, 0.f), acc0);
            acc0 = fmaf(s4.y, fmaxf(a4.y + t0.y, 0.f), acc0);
            acc0 = fmaf(s4.z, fmaxf(a4.z + t0.z, 0.f), acc0);
            acc0 = fmaf(s4.w, fmaxf(a4.w + t0.w, 0.f), acc0);
            acc1 = fmaf(s4.x, fmaxf(a4.x + t1.x, 0.f), acc1);
            acc1 = fmaf(s4.y, fmaxf(a4.y + t1.y, 0.f), acc1);
            acc1 = fmaf(s4.z, fmaxf(a4.z + t1.z, 0.f), acc1);
            acc1 = fmaf(s4.w, fmaxf(a4.w + t1.w, 0.f), acc1);
        }
        const int mg0 = mt + m0, mg1 = mt + m0 + 32;
        float sc0 = fmaf(ALPHA, a_n + sh_atgt[mg0], acc0);
        float sc1 = fmaf(ALPHA, a_n + sh_atgt[mg1], acc1);
        if (adj[adjRow + mg0] == 0) sc0 += -1.0e9f;
        if (adj[adjRow + mg1] == 0) sc1 += -1.0e9f;
        sh_sc[n_loc][mg0] = sc0;
        sh_sc[n_loc][mg1] = sc1;
        __syncthreads();
    }

    // ---- softmax (unnormalized; keep 1/sum) ----
    {
        const int w = t >> 5, lane = t & 31;
        float mx = -3.4e38f;
#pragma unroll
        for (int m = lane; m < NN; m += 32) mx = fmaxf(mx, sh_sc[w][m]);
#pragma unroll
        for (int off = 16; off; off >>= 1)
            mx = fmaxf(mx, __shfl_xor_sync(0xffffffffu, mx, off));
        float sum = 0.f;
#pragma unroll
        for (int m = lane; m < NN; m += 32) {
            float p = __expf(sh_sc[w][m] - mx);
            sh_sc[w][m] = p;
            sum += p;
        }
#pragma unroll
        for (int off = 16; off; off >>= 1)
            sum += __shfl_xor_sync(0xffffffffu, sum, off);
        if (lane == 0) sh_inv[w] = 1.f / sum;
    }
    __syncthreads();

    // ---- phase 2: aggregation (values = src rows) ----
    const int half = t >> 7;             // m-range split
    const int n0   = ((t >> 5) & 3) * 2; // 2 query rows
    const int d0   = (t & 31) * 2;       // 2 feature cols
    float acc00 = 0.f, acc01 = 0.f, acc10 = 0.f, acc11 = 0.f;

    for (int mt = 0; mt < NN; mt += 64) {
#pragma unroll
        for (int i = 0; i < 4; i++) {
            int idx = t + i * 256;
            int r = idx >> 4, c4 = idx & 15;
            *(float4*)&sh_t[r][c4 * 4] =
                *(const float4*)&g_src[(size_t)(b * NN + mt + r) * HD + h * 64 + c4 * 4];
        }
        __syncthreads();

        const int ms = half * 32;
        const float* p0r = &sh_sc[n0][mt + ms];
        const float* p1r = &sh_sc[n0 + 1][mt + ms];
#pragma unroll 8
        for (int mm = 0; mm < 32; mm++) {
            float p0 = p0r[mm], p1 = p1r[mm];
            float2 v = *(const float2*)&sh_t[ms + mm][d0];
            acc00 = fmaf(p0, v.x, acc00);
            acc01 = fmaf(p0, v.y, acc01);
            acc10 = fmaf(p1, v.x, acc10);
            acc11 = fmaf(p1, v.y, acc11);
        }
        __syncthreads();
    }

    // combine the two m-halves via shared (sh_sc free after phase 2)
    if (half == 1) {
        sh_sc[n0][d0]     = acc00; sh_sc[n0][d0 + 1]     = acc01;
        sh_sc[n0 + 1][d0] = acc10; sh_sc[n0 + 1][d0 + 1] = acc11;
    }
    __syncthreads();
    if (half == 0) {
        acc00 += sh_sc[n0][d0];     acc01 += sh_sc[n0][d0 + 1];
        acc10 += sh_sc[n0 + 1][d0]; acc11 += sh_sc[n0 + 1][d0 + 1];
        const float inv0 = sh_inv[n0], inv1 = sh_inv[n0 + 1];
        const int col = h * 64 + d0;
        const size_t r0 = (size_t)(b * NN + nBase + n0) * HD + col;
        const size_t r1 = r0 + HD;
        const float bx = bias[col], by = bias[col + 1];
        float o;
        o = fmaf(acc00, inv0, g_skip[r0]     + bx); out[r0]     = (o > 0.f) ? o : expm1f(o);
        o = fmaf(acc01, inv0, g_skip[r0 + 1] + by); out[r0 + 1] = (o > 0.f) ? o : expm1f(o);
        o = fmaf(acc10, inv1, g_skip[r1]     + bx); out[r1]     = (o > 0.f) ? o : expm1f(o);
        o = fmaf(acc11, inv1, g_skip[r1 + 1] + by); out[r1 + 1] = (o > 0.f) ? o : expm1f(o);
    }
}

// Optional second output: reference returns (out, adj)
__global__ void __launch_bounds__(256) copy_adj_kernel(
    const int* __restrict__ adj, float* __restrict__ dst, int n)
{
    int i = blockIdx.x * 256 + threadIdx.x;
    if (i < n) dst[i] = (float)adj[i];
}

extern "C" void kernel_launch(void* const* d_in, const int* in_sizes, int n_in,
                              void* d_out, int out_size)
{
    const float* x       = (const float*)d_in[0];
    const int*   adj     = (const int*)  d_in[1];
    const float* Wsrc    = (const float*)d_in[2];
    const float* Wtgt    = (const float*)d_in[3];
    const float* Wskip   = (const float*)d_in[4];
    const float* scoring = (const float*)d_in[5];
    const float* bias    = (const float*)d_in[6];
    float* out = (float*)d_out;

    gemm3_kernel<<<dim3(HD / 64, ROWS / 64, 3), 256>>>(x, Wsrc, Wtgt, Wskip);
    rank1_kernel<<<ROWS, 256>>>(scoring);
    attn_kernel<<<dim3(NN / 8, HEADS, BSZ), 256>>>(adj, scoring, bias, out);

    const int main_elems = ROWS * HD;               // 524288
    if (out_size > main_elems) {
        int extra = out_size - main_elems;
        const int adj_elems = BSZ * NN * NN;        // 524288
        if (extra > adj_elems) extra = adj_elems;
        copy_adj_kernel<<<(extra + 255) / 256, 256>>>(adj, out + main_elems, extra);
    }
}

// round 3
// speedup vs baseline: 1.0769x; 1.0769x over previous
#include <cuda_runtime.h>
#include <math.h>

#define BSZ   2
#define NN    512
#define DIN   256
#define HEADS 8
#define DOUT  64
#define HD    512
#define ROWS  1024
#define ALPHA 0.2f

// ---------------- packed fp32x2 helpers (Blackwell FADD2/FFMA2) ----------------
struct __align__(8) F2 { float x, y; };

__device__ __forceinline__ F2 f2add(F2 a, F2 b) {
    F2 r;
    asm("add.rn.f32x2 %0, %1, %2;"
        : "=l"(*reinterpret_cast<unsigned long long*>(&r))
        : "l"(*reinterpret_cast<unsigned long long*>(&a)),
          "l"(*reinterpret_cast<unsigned long long*>(&b)));
    return r;
}
__device__ __forceinline__ F2 f2fma(F2 a, F2 b, F2 c) {
    F2 r;
    asm("fma.rn.f32x2 %0, %1, %2, %3;"
        : "=l"(*reinterpret_cast<unsigned long long*>(&r))
        : "l"(*reinterpret_cast<unsigned long long*>(&a)),
          "l"(*reinterpret_cast<unsigned long long*>(&b)),
          "l"(*reinterpret_cast<unsigned long long*>(&c)));
    return r;
}

// ---------------- device scratch ----------------
__device__ float g_src [ROWS * HD];
__device__ float g_tgt [ROWS * HD];
__device__ float g_skip[ROWS * HD];
__device__ float g_asrc[BSZ * HEADS * NN];
__device__ float g_atgt[BSZ * HEADS * NN];

// ---------------------------------------------------------------------------
// K1: three projections C = X @ W (X:[1024,256], W:[256,512])
// 128x64 tile, k-slab 16, 256 threads, 8x4 micro (FFMA2), A pre-duplicated.
// Epilogue (z<2): rank-1 dots s_h . row -> g_asrc / g_atgt.
// ---------------------------------------------------------------------------
__global__ void __launch_bounds__(256) gemm3_kernel(
    const float* __restrict__ X,
    const float* __restrict__ Wsrc,
    const float* __restrict__ Wtgt,
    const float* __restrict__ Wskip,
    const float* __restrict__ scoring)
{
    __shared__ __align__(16) F2    As2[16][130];
    __shared__ __align__(16) float Bs [16][68];
    __shared__ float sh_sv[64];

    const int z = blockIdx.z;
    const float* W = (z == 0) ? Wsrc : (z == 1) ? Wtgt : Wskip;
    float* C = (z == 0) ? g_src : (z == 1) ? g_tgt : g_skip;

    const int rowBase = blockIdx.y * 128;
    const int colBase = blockIdx.x * 64;
    const int t  = threadIdx.x;
    const int nG = t >> 4;          // 0..15 -> 8 rows each
    const int dG = t & 15;          // 0..15 -> 4 cols each
    const int rG0 = nG * 8;
    const int d0  = dG * 4;

    if (t < 16)
        *(float4*)&sh_sv[t * 4] = *(const float4*)&scoring[colBase + t * 4];

    F2 acc[8][2];
#pragma unroll
    for (int i = 0; i < 8; i++) { acc[i][0] = {0.f, 0.f}; acc[i][1] = {0.f, 0.f}; }

    for (int k0 = 0; k0 < DIN; k0 += 16) {
        __syncthreads();
#pragma unroll
        for (int i = 0; i < 8; i++) {
            int idx = i * 256 + t;
            int row = idx >> 4, kk = idx & 15;
            float v = X[(size_t)(rowBase + row) * DIN + k0 + kk];
            As2[kk][row] = {v, v};
        }
        {
            int kk = t >> 4, c4 = t & 15;
            *(float4*)&Bs[kk][c4 * 4] =
                *(const float4*)&W[(size_t)(k0 + kk) * HD + colBase + c4 * 4];
        }
        __syncthreads();

#pragma unroll
        for (int k = 0; k < 16; k++) {
            float4 bv = *(const float4*)&Bs[k][d0];
            F2 b01 = {bv.x, bv.y};
            F2 b23 = {bv.z, bv.w};
#pragma unroll
            for (int rp = 0; rp < 4; rp++) {
                float4 av = *(const float4*)&As2[k][rG0 + 2 * rp]; // 2 dup'd pairs
                F2 a0 = {av.x, av.y};
                F2 a1 = {av.z, av.w};
                acc[2*rp][0]   = f2fma(a0, b01, acc[2*rp][0]);
                acc[2*rp][1]   = f2fma(a0, b23, acc[2*rp][1]);
                acc[2*rp+1][0] = f2fma(a1, b01, acc[2*rp+1][0]);
                acc[2*rp+1][1] = f2fma(a1, b23, acc[2*rp+1][1]);
            }
        }
    }

#pragma unroll
    for (int i = 0; i < 8; i++) {
        float4 v = make_float4(acc[i][0].x, acc[i][0].y, acc[i][1].x, acc[i][1].y);
        *(float4*)&C[(size_t)(rowBase + rG0 + i) * HD + colBase + d0] = v;
    }

    if (z < 2) {
        const float s0 = sh_sv[d0], s1 = sh_sv[d0+1], s2 = sh_sv[d0+2], s3 = sh_sv[d0+3];
        float part[8];
#pragma unroll
        for (int i = 0; i < 8; i++)
            part[i] = acc[i][0].x * s0 + acc[i][0].y * s1
                    + acc[i][1].x * s2 + acc[i][1].y * s3;
#pragma unroll
        for (int o = 1; o <= 8; o <<= 1)
#pragma unroll
            for (int i = 0; i < 8; i++)
                part[i] += __shfl_xor_sync(0xffffffffu, part[i], o);
        if (dG == 0) {
            float* dst = (z == 0) ? g_asrc : g_atgt;
            const int hh = colBase >> 6;
#pragma unroll
            for (int i = 0; i < 8; i++) {
                int rG = rowBase + rG0 + i;
                dst[((rG >> 9) * HEADS + hh) * NN + (rG & (NN - 1))] = part[i];
            }
        }
    }
}

// ---------------------------------------------------------------------------
// K2: fused scores + mask + softmax + aggregation + skip + bias + ELU
// Block = (16 query rows, head, batch); 256 threads. Grid (32, 8, 2).
// ---------------------------------------------------------------------------
#define PPITCH 517   // probs row pitch (bank-conflict-avoiding)
#define TPITCH 10    // tgt-stage row pitch (floats)
#define VPITCH 68    // value tile row pitch

__global__ void __launch_bounds__(256) attn_kernel(
    const int*   __restrict__ adj,
    const float* __restrict__ scoring,
    const float* __restrict__ bias,
    float*       __restrict__ out)
{
    // BUF: phase1 tgt stage (512*10) -> probs [16][517] -> reduction overlay [8][1024]
    __shared__ __align__(16) float BUF [16 * PPITCH];   // 8272 floats
    __shared__ __align__(16) float VBUF[32 * VPITCH];   // 2176 floats
    __shared__ __align__(16) float sh_src[16 * 64];
    __shared__ float sh_atgt[512];
    __shared__ __align__(16) float sh_s[64];
    __shared__ float sh_asrc[16];
    __shared__ float sh_inv[16];
    __shared__ float REDM[4][2][4];
    __shared__ float REDS[4][2][4];

    const int t  = threadIdx.x;
    const int bn = blockIdx.x * 16;
    const int h  = blockIdx.y;
    const int b  = blockIdx.z;
    const int bh = b * HEADS + h;

    const int nG = t >> 6;      // 0..3 (4 n each)
    const int mG = t & 63;      // m = mG + 64*mm (strided)
    const int w  = (t >> 5) & 1;

    // ---- prologue ----
    if (t < 16) {
        float4 v = *(const float4*)&scoring[h * 64 + t * 4];
        v.x *= (1.f - ALPHA); v.y *= (1.f - ALPHA);
        v.z *= (1.f - ALPHA); v.w *= (1.f - ALPHA);
        *(float4*)&sh_s[t * 4] = v;
        sh_asrc[t] = g_asrc[bh * NN + bn + t];
    }
    {
        int r = t >> 4, c = t & 15;
        *(float4*)&sh_src[r * 64 + c * 4] =
            *(const float4*)&g_src[(size_t)(b * NN + bn + r) * HD + h * 64 + c * 4];
    }
    sh_atgt[t]       = g_atgt[bh * NN + t];
    sh_atgt[t + 256] = g_atgt[bh * NN + t + 256];

    // ---- phase 1: scores (4n x 8m per thread, d chunks of 8, j-outer) ----
    F2 acc[4][8];
#pragma unroll
    for (int i = 0; i < 4; i++)
#pragma unroll
        for (int mm = 0; mm < 8; mm++) acc[i][mm] = {0.f, 0.f};

    for (int chunk = 0; chunk < 8; chunk++) {
        __syncthreads();
#pragma unroll
        for (int q = 0; q < 4; q++) {
            int f4 = t + 256 * q;
            int row = f4 >> 1, half = f4 & 1;
            float4 v = *(const float4*)
                &g_tgt[(size_t)(b * NN + row) * HD + h * 64 + chunk * 8 + half * 4];
            int base = row * TPITCH + half * 4;
            *(F2*)&BUF[base]     = {v.x, v.y};
            *(F2*)&BUF[base + 2] = {v.z, v.w};
        }
        __syncthreads();

#pragma unroll
        for (int j = 0; j < 4; j++) {
            F2 sj = *(const F2*)&sh_s[chunk * 8 + j * 2];
            F2 srcv[4];
#pragma unroll
            for (int i = 0; i < 4; i++)
                srcv[i] = *(const F2*)&sh_src[(nG * 4 + i) * 64 + chunk * 8 + j * 2];
#pragma unroll
            for (int mm = 0; mm < 8; mm++) {
                F2 tv = *(const F2*)&BUF[(mG + 64 * mm) * TPITCH + j * 2];
#pragma unroll
                for (int i = 0; i < 4; i++) {
                    F2 u = f2add(srcv[i], tv);
                    u.x = fmaxf(u.x, 0.f);
                    u.y = fmaxf(u.y, 0.f);
                    acc[i][mm] = f2fma(sj, u, acc[i][mm]);
                }
            }
        }
    }

    // ---- finalize scores: alpha-term + mask ----
    float a_n[4];
#pragma unroll
    for (int i = 0; i < 4; i++) a_n[i] = sh_asrc[nG * 4 + i];

    float sc[4][8];
#pragma unroll
    for (int mm = 0; mm < 8; mm++) {
        const int m = mG + 64 * mm;
        const float bm = sh_atgt[m];
#pragma unroll
        for (int i = 0; i < 4; i++) {
            float s = acc[i][mm].x + acc[i][mm].y;
            s = fmaf(ALPHA, a_n[i] + bm, s);
            int av = adj[(size_t)(b * NN + bn + nG * 4 + i) * NN + m];
            sc[i][mm] = (av == 0) ? s - 1.0e9f : s;
        }
    }

    // ---- softmax reductions ----
    float rm[4];
#pragma unroll
    for (int i = 0; i < 4; i++) {
        float v = sc[i][0];
#pragma unroll
        for (int mm = 1; mm < 8; mm++) v = fmaxf(v, sc[i][mm]);
#pragma unroll
        for (int o = 16; o; o >>= 1)
            v = fmaxf(v, __shfl_xor_sync(0xffffffffu, v, o));
        rm[i] = v;
    }
    if ((t & 31) == 0)
#pragma unroll
        for (int i = 0; i < 4; i++) REDM[nG][w][i] = rm[i];
    __syncthreads();   // also: BUF (tgt stage) now dead -> reusable as probs
#pragma unroll
    for (int i = 0; i < 4; i++) rm[i] = fmaxf(REDM[nG][0][i], REDM[nG][1][i]);

    float ps[4] = {0.f, 0.f, 0.f, 0.f};
#pragma unroll
    for (int mm = 0; mm < 8; mm++) {
        const int m = mG + 64 * mm;
#pragma unroll
        for (int i = 0; i < 4; i++) {
            float p = __expf(sc[i][mm] - rm[i]);
            BUF[(nG * 4 + i) * PPITCH + m] = p;
            ps[i] += p;
        }
    }
#pragma unroll
    for (int i = 0; i < 4; i++)
#pragma unroll
        for (int o = 16; o; o >>= 1)
            ps[i] += __shfl_xor_sync(0xffffffffu, ps[i], o);
    if ((t & 31) == 0)
#pragma unroll
        for (int i = 0; i < 4; i++) REDS[nG][w][i] = ps[i];
    __syncthreads();
    if (t < 16)
        sh_inv[t] = 1.f / (REDS[t >> 2][0][t & 3] + REDS[t >> 2][1][t & 3]);

    // ---- phase 2: aggregation (8-way m split, 4n x 8d per lane) ----
    const int g    = t >> 5;
    const int l    = t & 31;
    const int nSub = l >> 3;
    const int dSub = l & 7;

    F2 acc2[4][4];
#pragma unroll
    for (int i = 0; i < 4; i++)
#pragma unroll
        for (int j = 0; j < 4; j++) acc2[i][j] = {0.f, 0.f};

    for (int tile = 0; tile < 16; tile++) {
        __syncthreads();
#pragma unroll
        for (int q = 0; q < 2; q++) {
            int f4 = t + 256 * q;
            int row = f4 >> 4, c = f4 & 15;
            *(float4*)&VBUF[row * VPITCH + c * 4] = *(const float4*)
                &g_src[(size_t)(b * NN + tile * 32 + row) * HD + h * 64 + c * 4];
        }
        __syncthreads();

#pragma unroll
        for (int mm = 0; mm < 4; mm++) {
            const int mloc = g * 4 + mm;
            const int m = tile * 32 + mloc;
            F2 vv[4];
#pragma unroll
            for (int j = 0; j < 4; j++)
                vv[j] = *(const F2*)&VBUF[mloc * VPITCH + dSub * 8 + 2 * j];
#pragma unroll
            for (int i = 0; i < 4; i++) {
                float p = BUF[(nSub * 4 + i) * PPITCH + m];
                F2 pp = {p, p};
#pragma unroll
                for (int j = 0; j < 4; j++)
                    acc2[i][j] = f2fma(pp, vv[j], acc2[i][j]);
            }
        }
    }

    __syncthreads();   // probs dead -> BUF reusable as reduction overlay
#pragma unroll
    for (int i = 0; i < 4; i++)
#pragma unroll
        for (int j = 0; j < 4; j++)
            *(F2*)&BUF[g * 1024 + (nSub * 4 + i) * 64 + dSub * 8 + 2 * j] = acc2[i][j];
    __syncthreads();

    // ---- final reduce + epilogue ----
    {
        const int oIdx = t * 4;
        const int n = oIdx >> 6, d = oIdx & 63;
        float4 s = make_float4(0.f, 0.f, 0.f, 0.f);
#pragma unroll
        for (int g2 = 0; g2 < 8; g2++) {
            float4 r = *(const float4*)&BUF[g2 * 1024 + oIdx];
            s.x += r.x; s.y += r.y; s.z += r.z; s.w += r.w;
        }
        const float inv = sh_inv[n];
        const size_t off = (size_t)(b * NN + bn + n) * HD + h * 64 + d;
        float4 sk = *(const float4*)&g_skip[off];
        float4 bi = *(const float4*)&bias[h * 64 + d];
        float4 o;
        o.x = fmaf(s.x, inv, sk.x + bi.x);
        o.y = fmaf(s.y, inv, sk.y + bi.y);
        o.z = fmaf(s.z, inv, sk.z + bi.z);
        o.w = fmaf(s.w, inv, sk.w + bi.w);
        o.x = (o.x > 0.f) ? o.x : expm1f(o.x);
        o.y = (o.y > 0.f) ? o.y : expm1f(o.y);
        o.z = (o.z > 0.f) ? o.z : expm1f(o.z);
        o.w = (o.w > 0.f) ? o.w : expm1f(o.w);
        *(float4*)&out[off] = o;
    }
}

// ---------------------------------------------------------------------------
// Optional second output: reference returns (out, adj)
// ---------------------------------------------------------------------------
__global__ void __launch_bounds__(256) copy_adj_vec_kernel(
    const int4* __restrict__ adj, float4* __restrict__ dst, int n4)
{
    int i = blockIdx.x * 256 + threadIdx.x;
    if (i < n4) {
        int4 v = adj[i];
        dst[i] = make_float4((float)v.x, (float)v.y, (float)v.z, (float)v.w);
    }
}
__global__ void copy_adj_tail_kernel(
    const int* __restrict__ adj, float* __restrict__ dst, int off, int n)
{
    int i = blockIdx.x * 256 + threadIdx.x;
    if (i < n) dst[off + i] = (float)adj[off + i];
}

extern "C" void kernel_launch(void* const* d_in, const int* in_sizes, int n_in,
                              void* d_out, int out_size)
{
    const float* x       = (const float*)d_in[0];
    const int*   adj     = (const int*)  d_in[1];
    const float* Wsrc    = (const float*)d_in[2];
    const float* Wtgt    = (const float*)d_in[3];
    const float* Wskip   = (const float*)d_in[4];
    const float* scoring = (const float*)d_in[5];
    const float* bias    = (const float*)d_in[6];
    float* out = (float*)d_out;

    gemm3_kernel<<<dim3(HD / 64, ROWS / 128, 3), 256>>>(x, Wsrc, Wtgt, Wskip, scoring);
    attn_kernel<<<dim3(NN / 16, HEADS, BSZ), 256>>>(adj, scoring, bias, out);

    const int main_elems = ROWS * HD;               // 524288
    if (out_size > main_elems) {
        int extra = out_size - main_elems;
        const int adj_elems = BSZ * NN * NN;        // 524288
        if (extra > adj_elems) extra = adj_elems;
        int n4 = extra >> 2;
        if (n4 > 0)
            copy_adj_vec_kernel<<<(n4 + 255) / 256, 256>>>(
                (const int4*)adj, (float4*)(out + main_elems), n4);
        int rem = extra - (n4 << 2);
        if (rem > 0)
            copy_adj_tail_kernel<<<1, 256>>>(adj, out + main_elems, n4 << 2, rem);
    }
}

// round 4
// speedup vs baseline: 1.1503x; 1.0681x over previous
#include <cuda_runtime.h>
#include <math.h>

#define BSZ   2
#define NN    512
#define DIN   256
#define HEADS 8
#define DOUT  64
#define HD    512
#define ROWS  1024
#define ALPHA 0.2f

// ---------------- packed fp32x2 helpers (Blackwell FADD2/FFMA2) ----------------
struct __align__(8) F2 { float x, y; };

__device__ __forceinline__ F2 f2add(F2 a, F2 b) {
    F2 r;
    asm("add.rn.f32x2 %0, %1, %2;"
        : "=l"(*reinterpret_cast<unsigned long long*>(&r))
        : "l"(*reinterpret_cast<unsigned long long*>(&a)),
          "l"(*reinterpret_cast<unsigned long long*>(&b)));
    return r;
}
__device__ __forceinline__ F2 f2fma(F2 a, F2 b, F2 c) {
    F2 r;
    asm("fma.rn.f32x2 %0, %1, %2, %3;"
        : "=l"(*reinterpret_cast<unsigned long long*>(&r))
        : "l"(*reinterpret_cast<unsigned long long*>(&a)),
          "l"(*reinterpret_cast<unsigned long long*>(&b)),
          "l"(*reinterpret_cast<unsigned long long*>(&c)));
    return r;
}

// ---------------- device scratch ----------------
__device__ float g_src [ROWS * HD];
__device__ float g_tgt [ROWS * HD];
__device__ float g_skip[ROWS * HD];
__device__ float g_asrc[BSZ * HEADS * NN];
__device__ float g_atgt[BSZ * HEADS * NN];

// ---------------------------------------------------------------------------
// K1: three projections C = X @ W (X:[1024,256], W:[256,512])
// 64x64 tile, 128 threads, grid (8,16,3)=384 blocks.
// Accumulators packed along n (no A duplication). k-slab 32, reg-prefetch.
// Epilogue (z<2): rank-1 dots s_h . row -> g_asrc / g_atgt.
// ---------------------------------------------------------------------------
#define APITCH 68
#define BPITCH 68

__global__ void __launch_bounds__(128) gemm3_kernel(
    const float* __restrict__ X,
    const float* __restrict__ Wsrc,
    const float* __restrict__ Wtgt,
    const float* __restrict__ Wskip,
    const float* __restrict__ scoring)
{
    __shared__ __align__(16) float As[32 * APITCH];  // [kk][n]
    __shared__ __align__(16) float Bs[32 * BPITCH];  // [kk][d]
    __shared__ float sh_sv[64];

    const int z = blockIdx.z;
    const float* W = (z == 0) ? Wsrc : (z == 1) ? Wtgt : Wskip;
    float* C = (z == 0) ? g_src : (z == 1) ? g_tgt : g_skip;

    const int rowBase = blockIdx.y * 64;
    const int colBase = blockIdx.x * 64;
    const int t  = threadIdx.x;

    const int nG = t >> 4;            // 0..7 -> 8 rows (4 n-pairs)
    const int dG = t & 15;            // 0..15 -> 4 cols
    const int r0 = nG * 8;
    const int d0 = dG * 4;

    // loader mapping
    const int ak = t & 31;            // k within slab (A)
    const int an = t >> 5;            // n base 0..3 (+4i)
    const int bk = t >> 4;            // k base 0..7 (+8i) (B)
    const int bd = (t & 15) * 4;      // d (float4)

    if (t < 16)
        *(float4*)&sh_sv[t * 4] = *(const float4*)&scoring[colBase + t * 4];

    F2 acc[4][4];
#pragma unroll
    for (int p = 0; p < 4; p++)
#pragma unroll
        for (int j = 0; j < 4; j++) acc[p][j] = {0.f, 0.f};

    float  aR[16];
    float4 bR[4];

    // prefetch slab 0
#pragma unroll
    for (int i = 0; i < 16; i++)
        aR[i] = X[(size_t)(rowBase + an + 4 * i) * DIN + ak];
#pragma unroll
    for (int i = 0; i < 4; i++)
        bR[i] = *(const float4*)&W[(size_t)(bk + 8 * i) * HD + colBase + bd];

    for (int s = 0; s < 8; s++) {
        __syncthreads();
#pragma unroll
        for (int i = 0; i < 16; i++)
            As[ak * APITCH + an + 4 * i] = aR[i];
#pragma unroll
        for (int i = 0; i < 4; i++)
            *(float4*)&Bs[(bk + 8 * i) * BPITCH + bd] = bR[i];
        __syncthreads();

        if (s < 7) {
            const int k0 = (s + 1) * 32;
#pragma unroll
            for (int i = 0; i < 16; i++)
                aR[i] = X[(size_t)(rowBase + an + 4 * i) * DIN + k0 + ak];
#pragma unroll
            for (int i = 0; i < 4; i++)
                bR[i] = *(const float4*)&W[(size_t)(k0 + bk + 8 * i) * HD + colBase + bd];
        }

#pragma unroll
        for (int k = 0; k < 32; k++) {
            float4 a01 = *(const float4*)&As[k * APITCH + r0];
            float4 a23 = *(const float4*)&As[k * APITCH + r0 + 4];
            float4 b   = *(const float4*)&Bs[k * BPITCH + d0];
            F2 ap[4] = {{a01.x, a01.y}, {a01.z, a01.w}, {a23.x, a23.y}, {a23.z, a23.w}};
            F2 bb[4] = {{b.x, b.x}, {b.y, b.y}, {b.z, b.z}, {b.w, b.w}};
#pragma unroll
            for (int p = 0; p < 4; p++)
#pragma unroll
                for (int j = 0; j < 4; j++)
                    acc[p][j] = f2fma(ap[p], bb[j], acc[p][j]);
        }
    }

    // store C: 8 rows x 4 cols per thread
#pragma unroll
    for (int p = 0; p < 4; p++) {
        float4 lo = make_float4(acc[p][0].x, acc[p][1].x, acc[p][2].x, acc[p][3].x);
        float4 hi = make_float4(acc[p][0].y, acc[p][1].y, acc[p][2].y, acc[p][3].y);
        *(float4*)&C[(size_t)(rowBase + r0 + 2 * p)     * HD + colBase + d0] = lo;
        *(float4*)&C[(size_t)(rowBase + r0 + 2 * p + 1) * HD + colBase + d0] = hi;
    }

    if (z < 2) {
        const float s0 = sh_sv[d0], s1 = sh_sv[d0 + 1],
                    s2 = sh_sv[d0 + 2], s3 = sh_sv[d0 + 3];
        float part[8];
#pragma unroll
        for (int p = 0; p < 4; p++) {
            part[2 * p]     = acc[p][0].x * s0 + acc[p][1].x * s1
                            + acc[p][2].x * s2 + acc[p][3].x * s3;
            part[2 * p + 1] = acc[p][0].y * s0 + acc[p][1].y * s1
                            + acc[p][2].y * s2 + acc[p][3].y * s3;
        }
#pragma unroll
        for (int o = 1; o <= 8; o <<= 1)
#pragma unroll
            for (int i = 0; i < 8; i++)
                part[i] += __shfl_xor_sync(0xffffffffu, part[i], o);
        if (dG == 0) {
            float* dst = (z == 0) ? g_asrc : g_atgt;
            const int hh = colBase >> 6;
#pragma unroll
            for (int i = 0; i < 8; i++) {
                int rG = rowBase + r0 + i;
                dst[((rG >> 9) * HEADS + hh) * NN + (rG & (NN - 1))] = part[i];
            }
        }
    }
}

// ---------------------------------------------------------------------------
// K2: fused scores + mask + softmax + aggregation + skip + bias + ELU
// Block = (16 query rows, head, batch); 256 threads. Grid (32, 8, 2).
// ---------------------------------------------------------------------------
#define PPITCH 517
#define TPITCH 10
#define VPITCH 68

__global__ void __launch_bounds__(256) attn_kernel(
    const int*   __restrict__ adj,
    const float* __restrict__ scoring,
    const float* __restrict__ bias,
    float*       __restrict__ out)
{
    __shared__ __align__(16) float BUF [16 * PPITCH];   // tgt stage -> scores/probs -> overlay
    __shared__ __align__(16) float VBUF[32 * VPITCH];
    __shared__ __align__(16) float sh_src[16 * 64];
    __shared__ float sh_atgt[512];
    __shared__ __align__(16) float sh_s[64];
    __shared__ float sh_asrc[16];
    __shared__ float sh_inv[16];
    __shared__ float REDM[4][2][4];
    __shared__ float REDS[4][2][4];

    const int t  = threadIdx.x;
    const int bn = blockIdx.x * 16;
    const int h  = blockIdx.y;
    const int b  = blockIdx.z;
    const int bh = b * HEADS + h;

    const int nG = t >> 6;      // 0..3 (4 n each)
    const int mG = t & 63;      // m = mG + 64*mm
    const int w  = (t >> 5) & 1;

    // ---- prologue ----
    if (t < 16) {
        float4 v = *(const float4*)&scoring[h * 64 + t * 4];
        v.x *= (1.f - ALPHA); v.y *= (1.f - ALPHA);
        v.z *= (1.f - ALPHA); v.w *= (1.f - ALPHA);
        *(float4*)&sh_s[t * 4] = v;
        sh_asrc[t] = g_asrc[bh * NN + bn + t];
    }
    {
        int r = t >> 4, c = t & 15;
        *(float4*)&sh_src[r * 64 + c * 4] =
            *(const float4*)&g_src[(size_t)(b * NN + bn + r) * HD + h * 64 + c * 4];
    }
    sh_atgt[t]       = g_atgt[bh * NN + t];
    sh_atgt[t + 256] = g_atgt[bh * NN + t + 256];

    // ---- phase 1: scores (4n x 8m per thread, d chunks of 8, reg-prefetched) ----
    F2 acc[4][8];
#pragma unroll
    for (int i = 0; i < 4; i++)
#pragma unroll
        for (int mm = 0; mm < 8; mm++) acc[i][mm] = {0.f, 0.f};

    float4 pf[4];
#pragma unroll
    for (int q = 0; q < 4; q++) {
        int f4 = t + 256 * q;
        int row = f4 >> 1, half = f4 & 1;
        pf[q] = *(const float4*)&g_tgt[(size_t)(b * NN + row) * HD + h * 64 + half * 4];
    }

    for (int chunk = 0; chunk < 8; chunk++) {
        __syncthreads();
#pragma unroll
        for (int q = 0; q < 4; q++) {
            int f4 = t + 256 * q;
            int row = f4 >> 1, half = f4 & 1;
            int base = row * TPITCH + half * 4;
            *(F2*)&BUF[base]     = {pf[q].x, pf[q].y};
            *(F2*)&BUF[base + 2] = {pf[q].z, pf[q].w};
        }
        __syncthreads();

        if (chunk < 7) {
            const int c8 = (chunk + 1) * 8;
#pragma unroll
            for (int q = 0; q < 4; q++) {
                int f4 = t + 256 * q;
                int row = f4 >> 1, half = f4 & 1;
                pf[q] = *(const float4*)
                    &g_tgt[(size_t)(b * NN + row) * HD + h * 64 + c8 + half * 4];
            }
        }

#pragma unroll
        for (int j = 0; j < 4; j++) {
            F2 sj = *(const F2*)&sh_s[chunk * 8 + j * 2];
            F2 srcv[4];
#pragma unroll
            for (int i = 0; i < 4; i++)
                srcv[i] = *(const F2*)&sh_src[(nG * 4 + i) * 64 + chunk * 8 + j * 2];
#pragma unroll
            for (int mm = 0; mm < 8; mm++) {
                F2 tv = *(const F2*)&BUF[(mG + 64 * mm) * TPITCH + j * 2];
#pragma unroll
                for (int i = 0; i < 4; i++) {
                    F2 u = f2add(srcv[i], tv);
                    u.x = fmaxf(u.x, 0.f);
                    u.y = fmaxf(u.y, 0.f);
                    acc[i][mm] = f2fma(sj, u, acc[i][mm]);
                }
            }
        }
    }
    __syncthreads();   // last tgt-stage reads complete; BUF -> score buffer

    // ---- finalize scores: alpha-term + mask, store to BUF, track max ----
    float a_n[4];
#pragma unroll
    for (int i = 0; i < 4; i++) a_n[i] = sh_asrc[nG * 4 + i];

    float rm[4] = {-3.4e38f, -3.4e38f, -3.4e38f, -3.4e38f};
#pragma unroll
    for (int mm = 0; mm < 8; mm++) {
        const int m = mG + 64 * mm;
        const float bm = sh_atgt[m];
#pragma unroll
        for (int i = 0; i < 4; i++) {
            float s = acc[i][mm].x + acc[i][mm].y;
            s = fmaf(ALPHA, a_n[i] + bm, s);
            int av = adj[(size_t)(b * NN + bn + nG * 4 + i) * NN + m];
            s = (av == 0) ? s - 1.0e9f : s;
            BUF[(nG * 4 + i) * PPITCH + m] = s;
            rm[i] = fmaxf(rm[i], s);
        }
    }
#pragma unroll
    for (int i = 0; i < 4; i++)
#pragma unroll
        for (int o = 16; o; o >>= 1)
            rm[i] = fmaxf(rm[i], __shfl_xor_sync(0xffffffffu, rm[i], o));
    if ((t & 31) == 0)
#pragma unroll
        for (int i = 0; i < 4; i++) REDM[nG][w][i] = rm[i];
    __syncthreads();
#pragma unroll
    for (int i = 0; i < 4; i++) rm[i] = fmaxf(REDM[nG][0][i], REDM[nG][1][i]);

    // exp pass (in place) + sums
    float ps[4] = {0.f, 0.f, 0.f, 0.f};
#pragma unroll
    for (int mm = 0; mm < 8; mm++) {
        const int m = mG + 64 * mm;
#pragma unroll
        for (int i = 0; i < 4; i++) {
            float p = __expf(BUF[(nG * 4 + i) * PPITCH + m] - rm[i]);
            BUF[(nG * 4 + i) * PPITCH + m] = p;
            ps[i] += p;
        }
    }
#pragma unroll
    for (int i = 0; i < 4; i++)
#pragma unroll
        for (int o = 16; o; o >>= 1)
            ps[i] += __shfl_xor_sync(0xffffffffu, ps[i], o);
    if ((t & 31) == 0)
#pragma unroll
        for (int i = 0; i < 4; i++) REDS[nG][w][i] = ps[i];
    __syncthreads();
    if (t < 16)
        sh_inv[t] = 1.f / (REDS[t >> 2][0][t & 3] + REDS[t >> 2][1][t & 3]);

    // ---- phase 2: aggregation (8-way m split, 4n x 8d per lane), reg-prefetched ----
    const int g    = t >> 5;
    const int l    = t & 31;
    const int nSub = l >> 3;
    const int dSub = l & 7;

    F2 acc2[4][4];
#pragma unroll
    for (int i = 0; i < 4; i++)
#pragma unroll
        for (int j = 0; j < 4; j++) acc2[i][j] = {0.f, 0.f};

    float4 vf[2];
#pragma unroll
    for (int q = 0; q < 2; q++) {
        int f4 = t + 256 * q;
        int row = f4 >> 4, c = f4 & 15;
        vf[q] = *(const float4*)&g_src[(size_t)(b * NN + row) * HD + h * 64 + c * 4];
    }

    for (int tile = 0; tile < 16; tile++) {
        __syncthreads();
#pragma unroll
        for (int q = 0; q < 2; q++) {
            int f4 = t + 256 * q;
            int row = f4 >> 4, c = f4 & 15;
            *(float4*)&VBUF[row * VPITCH + c * 4] = vf[q];
        }
        __syncthreads();

        if (tile < 15) {
#pragma unroll
            for (int q = 0; q < 2; q++) {
                int f4 = t + 256 * q;
                int row = f4 >> 4, c = f4 & 15;
                vf[q] = *(const float4*)
                    &g_src[(size_t)(b * NN + (tile + 1) * 32 + row) * HD + h * 64 + c * 4];
            }
        }

#pragma unroll
        for (int mm = 0; mm < 4; mm++) {
            const int mloc = g * 4 + mm;
            const int m = tile * 32 + mloc;
            F2 vv[4];
#pragma unroll
            for (int j = 0; j < 4; j++)
                vv[j] = *(const F2*)&VBUF[mloc * VPITCH + dSub * 8 + 2 * j];
#pragma unroll
            for (int i = 0; i < 4; i++) {
                float p = BUF[(nSub * 4 + i) * PPITCH + m];
                F2 pp = {p, p};
#pragma unroll
                for (int j = 0; j < 4; j++)
                    acc2[i][j] = f2fma(pp, vv[j], acc2[i][j]);
            }
        }
    }

    __syncthreads();   // probs dead -> BUF reusable as reduction overlay
#pragma unroll
    for (int i = 0; i < 4; i++)
#pragma unroll
        for (int j = 0; j < 4; j++)
            *(F2*)&BUF[g * 1024 + (nSub * 4 + i) * 64 + dSub * 8 + 2 * j] = acc2[i][j];
    __syncthreads();

    // ---- final reduce + epilogue ----
    {
        const int oIdx = t * 4;
        const int n = oIdx >> 6, d = oIdx & 63;
        float4 s = make_float4(0.f, 0.f, 0.f, 0.f);
#pragma unroll
        for (int g2 = 0; g2 < 8; g2++) {
            float4 r = *(const float4*)&BUF[g2 * 1024 + oIdx];
            s.x += r.x; s.y += r.y; s.z += r.z; s.w += r.w;
        }
        const float inv = sh_inv[n];
        const size_t off = (size_t)(b * NN + bn + n) * HD + h * 64 + d;
        float4 sk = *(const float4*)&g_skip[off];
        float4 bi = *(const float4*)&bias[h * 64 + d];
        float4 o;
        o.x = fmaf(s.x, inv, sk.x + bi.x);
        o.y = fmaf(s.y, inv, sk.y + bi.y);
        o.z = fmaf(s.z, inv, sk.z + bi.z);
        o.w = fmaf(s.w, inv, sk.w + bi.w);
        o.x = (o.x > 0.f) ? o.x : expm1f(o.x);
        o.y = (o.y > 0.f) ? o.y : expm1f(o.y);
        o.z = (o.z > 0.f) ? o.z : expm1f(o.z);
        o.w = (o.w > 0.f) ? o.w : expm1f(o.w);
        *(float4*)&out[off] = o;
    }
}

// ---------------------------------------------------------------------------
// Optional second output: reference returns (out, adj)
// ---------------------------------------------------------------------------
__global__ void __launch_bounds__(256) copy_adj_vec_kernel(
    const int4* __restrict__ adj, float4* __restrict__ dst, int n4)
{
    int i = blockIdx.x * 256 + threadIdx.x;
    if (i < n4) {
        int4 v = adj[i];
        dst[i] = make_float4((float)v.x, (float)v.y, (float)v.z, (float)v.w);
    }
}
__global__ void copy_adj_tail_kernel(
    const int* __restrict__ adj, float* __restrict__ dst, int off, int n)
{
    int i = blockIdx.x * 256 + threadIdx.x;
    if (i < n) dst[off + i] = (float)adj[off + i];
}

extern "C" void kernel_launch(void* const* d_in, const int* in_sizes, int n_in,
                              void* d_out, int out_size)
{
    const float* x       = (const float*)d_in[0];
    const int*   adj     = (const int*)  d_in[1];
    const float* Wsrc    = (const float*)d_in[2];
    const float* Wtgt    = (const float*)d_in[3];
    const float* Wskip   = (const float*)d_in[4];
    const float* scoring = (const float*)d_in[5];
    const float* bias    = (const float*)d_in[6];
    float* out = (float*)d_out;

    gemm3_kernel<<<dim3(HD / 64, ROWS / 64, 3), 128>>>(x, Wsrc, Wtgt, Wskip, scoring);
    attn_kernel<<<dim3(NN / 16, HEADS, BSZ), 256>>>(adj, scoring, bias, out);

    const int main_elems = ROWS * HD;               // 524288
    if (out_size > main_elems) {
        int extra = out_size - main_elems;
        const int adj_elems = BSZ * NN * NN;        // 524288
        if (extra > adj_elems) extra = adj_elems;
        int n4 = extra >> 2;
        if (n4 > 0)
            copy_adj_vec_kernel<<<(n4 + 255) / 256, 256>>>(
                (const int4*)adj, (float4*)(out + main_elems), n4);
        int rem = extra - (n4 << 2);
        if (rem > 0)
            copy_adj_tail_kernel<<<1, 256>>>(adj, out + main_elems, n4 << 2, rem);
    }
}